// round 12
// baseline (speedup 1.0000x reference)
#include <cuda_runtime.h>

#define N_NODES 20000
#define N_EDGES 240000
#define IN_DIM  20
#define SH_DIM  16
#define OUT_DIM 360     // 20 (mlp) + 20 (sender sum) + 320 (tensor product)
#define CAP     64      // bucket capacity per node (max in-degree bound)

// ---- scratch (zero-initialized at module load; g_count invariant: ==0 on
//      entry to kernel_launch, restored by k_aggr each call) ----
__device__ __align__(16) int g_count[N_NODES];
__device__ __align__(16) int g_bucket[N_NODES * CAP];    // per-dest sender row ids

// ============================================================================
// K1: per-node MLP (output cols 0..19)
// ============================================================================
__global__ void k_mlp(const float* __restrict__ x,
                      const float* __restrict__ Wpre,  const float* __restrict__ bpre,
                      const float* __restrict__ Wpost, const float* __restrict__ bpost,
                      const float* __restrict__ Wsc,   const float* __restrict__ bsc,
                      float* __restrict__ out)
{
    __shared__ float sWpre[400], sWpost[400], sWsc[400], sb[60];
    for (int i = threadIdx.x; i < 400; i += blockDim.x) {
        sWpre[i]  = Wpre[i];
        sWpost[i] = Wpost[i];
        sWsc[i]   = Wsc[i];
    }
    if (threadIdx.x < 20) {
        sb[threadIdx.x]      = bpre[threadIdx.x];
        sb[20 + threadIdx.x] = bpost[threadIdx.x];
        sb[40 + threadIdx.x] = bsc[threadIdx.x];
    }
    __syncthreads();

    const int n = blockIdx.x * blockDim.x + threadIdx.x;
    if (n >= N_NODES) return;

    float xr[IN_DIM];
#pragma unroll
    for (int k = 0; k < IN_DIM; k++) xr[k] = x[n * IN_DIM + k];

    float pre[IN_DIM];
#pragma unroll
    for (int i = 0; i < IN_DIM; i++) {
        float a = sb[i];
#pragma unroll
        for (int k = 0; k < IN_DIM; k++) a = fmaf(xr[k], sWpre[i * IN_DIM + k], a);
        pre[i] = fmaxf(a, 0.0f);
    }

#pragma unroll
    for (int i = 0; i < IN_DIM; i++) {
        float a = sb[20 + i] + sb[40 + i];
#pragma unroll
        for (int k = 0; k < IN_DIM; k++) {
            a = fmaf(pre[k], sWpost[i * IN_DIM + k], a);
            a = fmaf(xr[k],  sWsc[i * IN_DIM + k],  a);
        }
        out[n * OUT_DIM + i] = a;
    }
}

// ============================================================================
// K2: fused histogram + bucket scatter — the atomic return IS the slot.
//     slot = col*CAP + atomicAdd(count[col]). 2 edges / thread, 16 regs,
//     full occupancy to hide the ATOMG latency.
// ============================================================================
__global__ void k_hist_scatter(const int* __restrict__ ei)
{
    const int i = blockIdx.x * blockDim.x + threadIdx.x;
    if (i >= N_EDGES / 2) return;
    const int2 r = __ldg(&((const int2*)ei)[i]);
    const int2 c = __ldg(&((const int2*)(ei + N_EDGES))[i]);
    const int rk0 = atomicAdd(&g_count[c.x], 1);
    const int rk1 = atomicAdd(&g_count[c.y], 1);
    g_bucket[(c.x << 6) + rk0] = r.x;
    g_bucket[(c.y << 6) + rk1] = r.y;
}

// ============================================================================
// K3: fused SH + gather-aggregate. One warp per destination node.
//     Reads degree from g_count and re-zeros it (restores replay invariant).
//     Chunk of 32 edges: phase 1 = lane-parallel SH into SMEM;
//     phase 2 = serial accumulate with broadcast LDS.128 SH reads.
// ============================================================================
#define WPB 8   // warps per block (256 threads)

__global__ void k_aggr3(const float* __restrict__ x,
                        const float* __restrict__ pos,
                        float* __restrict__ out)
{
    __shared__ float s_sh[WPB][32][20];   // [warp][edge][sh1..sh15, pad..]
    __shared__ int   s_r [WPB][32];

    const int warp = (blockIdx.x * blockDim.x + threadIdx.x) >> 5;
    const int w    = (threadIdx.x >> 5);
    const int lane = threadIdx.x & 31;
    if (warp >= N_NODES) return;
    const int n = warp;

    const int deg = g_count[n];
    if (lane == 0) g_count[n] = 0;        // restore invariant for next replay
    const int s0 = n << 6;                // bucket base
    const int s1 = s0 + deg;

    const float pnx = pos[n * 3 + 0];
    const float pny = pos[n * 3 + 1];
    const float pnz = pos[n * 3 + 2];

    float accS = 0.0f;
    float acc[15];
#pragma unroll
    for (int j = 0; j < 15; j++) acc[j] = 0.0f;

    for (int base = s0; base < s1; base += 32) {
        const int m = min(32, s1 - base);

        // ---- phase 1: lane-parallel SH for this chunk ----
        if (lane < m) {
            const int r = g_bucket[base + lane];       // coalesced within bucket
            s_r[w][lane] = r;
            float rx = pnx - pos[r * 3 + 0];
            float ry = pny - pos[r * 3 + 1];
            float rz = pnz - pos[r * 3 + 2];
            float inv = rsqrtf(fmaf(rx, rx, fmaf(ry, ry, fmaf(rz, rz, 1e-12f))));
            float X = rx * inv, Y = ry * inv, Z = rz * inv;
            float X2 = X * X, Y2 = Y * Y, Z2 = Z * Z;

            float4* q = (float4*)&s_sh[w][lane][0];
            q[0] = make_float4(0.4886025119029199f * Y,
                               0.4886025119029199f * Z,
                               0.4886025119029199f * X,
                               1.0925484305920792f * X * Y);
            q[1] = make_float4(1.0925484305920792f * Y * Z,
                               0.31539156525252005f * (3.0f * Z2 - 1.0f),
                               1.0925484305920792f * X * Z,
                               0.5462742152960396f * (X2 - Y2));
            q[2] = make_float4(0.5900435899266435f * Y * (3.0f * X2 - Y2),
                               2.890611442640554f  * X * Y * Z,
                               0.4570457994644658f * Y * (5.0f * Z2 - 1.0f),
                               0.3731763325901154f * Z * (5.0f * Z2 - 3.0f));
            q[3] = make_float4(0.4570457994644658f * X * (5.0f * Z2 - 1.0f),
                               1.445305721320277f  * Z * (X2 - Y2),
                               0.5900435899266435f * X * (X2 - 3.0f * Y2),
                               0.0f);
        }
        __syncwarp();

        // ---- phase 2: serial accumulate (2x unrolled) ----
        const float4* shA;
        const float4* shB;
        int t = 0;
        for (; t + 2 <= m; t += 2) {
            const int rA = s_r[w][t];
            const int rB = s_r[w][t + 1];
            const float sA = (lane < IN_DIM) ? __ldg(&x[rA * IN_DIM + lane]) : 0.0f;
            const float sB = (lane < IN_DIM) ? __ldg(&x[rB * IN_DIM + lane]) : 0.0f;
            shA = (const float4*)&s_sh[w][t][0];
            shB = (const float4*)&s_sh[w][t + 1][0];
            const float4 a0 = shA[0], a1 = shA[1], a2 = shA[2], a3 = shA[3];
            const float4 b0 = shB[0], b1 = shB[1], b2 = shB[2], b3 = shB[3];

            accS += sA + sB;
            acc[0]  = fmaf(sA, a0.x, fmaf(sB, b0.x, acc[0]));
            acc[1]  = fmaf(sA, a0.y, fmaf(sB, b0.y, acc[1]));
            acc[2]  = fmaf(sA, a0.z, fmaf(sB, b0.z, acc[2]));
            acc[3]  = fmaf(sA, a0.w, fmaf(sB, b0.w, acc[3]));
            acc[4]  = fmaf(sA, a1.x, fmaf(sB, b1.x, acc[4]));
            acc[5]  = fmaf(sA, a1.y, fmaf(sB, b1.y, acc[5]));
            acc[6]  = fmaf(sA, a1.z, fmaf(sB, b1.z, acc[6]));
            acc[7]  = fmaf(sA, a1.w, fmaf(sB, b1.w, acc[7]));
            acc[8]  = fmaf(sA, a2.x, fmaf(sB, b2.x, acc[8]));
            acc[9]  = fmaf(sA, a2.y, fmaf(sB, b2.y, acc[9]));
            acc[10] = fmaf(sA, a2.z, fmaf(sB, b2.z, acc[10]));
            acc[11] = fmaf(sA, a2.w, fmaf(sB, b2.w, acc[11]));
            acc[12] = fmaf(sA, a3.x, fmaf(sB, b3.x, acc[12]));
            acc[13] = fmaf(sA, a3.y, fmaf(sB, b3.y, acc[13]));
            acc[14] = fmaf(sA, a3.z, fmaf(sB, b3.z, acc[14]));
        }
        if (t < m) {
            const int rA = s_r[w][t];
            const float sA = (lane < IN_DIM) ? __ldg(&x[rA * IN_DIM + lane]) : 0.0f;
            shA = (const float4*)&s_sh[w][t][0];
            const float4 a0 = shA[0], a1 = shA[1], a2 = shA[2], a3 = shA[3];
            accS += sA;
            acc[0]  = fmaf(sA, a0.x, acc[0]);
            acc[1]  = fmaf(sA, a0.y, acc[1]);
            acc[2]  = fmaf(sA, a0.z, acc[2]);
            acc[3]  = fmaf(sA, a0.w, acc[3]);
            acc[4]  = fmaf(sA, a1.x, acc[4]);
            acc[5]  = fmaf(sA, a1.y, acc[5]);
            acc[6]  = fmaf(sA, a1.z, acc[6]);
            acc[7]  = fmaf(sA, a1.w, acc[7]);
            acc[8]  = fmaf(sA, a2.x, acc[8]);
            acc[9]  = fmaf(sA, a2.y, acc[9]);
            acc[10] = fmaf(sA, a2.z, acc[10]);
            acc[11] = fmaf(sA, a2.w, acc[11]);
            acc[12] = fmaf(sA, a3.x, acc[12]);
            acc[13] = fmaf(sA, a3.y, acc[13]);
            acc[14] = fmaf(sA, a3.z, acc[14]);
        }
        __syncwarp();
    }

    if (lane < IN_DIM) {
        float* base = out + n * OUT_DIM;
        base[20 + lane] = accS;
        float4* p = (float4*)(base + 40 + lane * SH_DIM);
        p[0] = make_float4(accS * 0.28209479177387814f, acc[0],  acc[1],  acc[2]);
        p[1] = make_float4(acc[3],  acc[4],  acc[5],  acc[6]);
        p[2] = make_float4(acc[7],  acc[8],  acc[9],  acc[10]);
        p[3] = make_float4(acc[11], acc[12], acc[13], acc[14]);
    }
}

// ============================================================================
extern "C" void kernel_launch(void* const* d_in, const int* in_sizes, int n_in,
                              void* d_out, int out_size)
{
    const float* x     = (const float*)d_in[0];
    const float* pos   = (const float*)d_in[1];
    const int*   ei    = (const int*)  d_in[2];
    const float* Wpre  = (const float*)d_in[3];
    const float* bpre  = (const float*)d_in[4];
    const float* Wpost = (const float*)d_in[5];
    const float* bpost = (const float*)d_in[6];
    const float* Wsc   = (const float*)d_in[7];
    const float* bsc   = (const float*)d_in[8];
    float* out = (float*)d_out;

    k_mlp         <<<(N_NODES + 255) / 256, 256>>>(x, Wpre, bpre, Wpost, bpost,
                                                   Wsc, bsc, out);
    k_hist_scatter<<<(N_EDGES / 2 + 255) / 256, 256>>>(ei);
    k_aggr3       <<<(N_NODES * 32 + 255) / 256, 256>>>(x, pos, out);
}

// round 13
// speedup vs baseline: 1.0137x; 1.0137x over previous
#include <cuda_runtime.h>

#define N_NODES 20000
#define N_EDGES 240000
#define IN_DIM  20
#define SH_DIM  16
#define OUT_DIM 360     // 20 (mlp) + 20 (sender sum) + 320 (tensor product)
#define CAP     64      // bucket capacity per node (max in-degree bound)

// ---- scratch (zero-initialized at module load; g_count invariant: ==0 on
//      entry to kernel_launch, restored by k_aggr each call) ----
__device__ __align__(16) int g_count[N_NODES];
__device__ __align__(16) int g_bucket[N_NODES * CAP];    // per-dest sender row ids

// ============================================================================
// K1: per-node MLP (output cols 0..19).
//     Thread = (node, output): 16 nodes x 20 outputs per 320-thread block,
//     12500 warps total (~21/SMSP) to hide LDS latency. Weights staged in
//     shared with stride 21 (coprime with 32 banks -> conflict-free).
// ============================================================================
#define NPB        16                    // nodes per block
#define MLP_THREADS (NPB * IN_DIM)       // 320
#define MLP_GRID   (N_NODES / NPB)       // 1250

__global__ void k_mlp(const float* __restrict__ x,
                      const float* __restrict__ Wpre,  const float* __restrict__ bpre,
                      const float* __restrict__ Wpost, const float* __restrict__ bpost,
                      const float* __restrict__ Wsc,   const float* __restrict__ bsc,
                      float* __restrict__ out)
{
    __shared__ float sWpre[IN_DIM * 21], sWpost[IN_DIM * 21], sWsc[IN_DIM * 21];
    __shared__ float sb[64];
    __shared__ float sx  [NPB * IN_DIM];        // x slab for this block's nodes
    __shared__ float spre[NPB * 21];            // relu(pre), padded stride 21

    const int tid = threadIdx.x;

    // stage weights (padded) and biases
    for (int idx = tid; idx < IN_DIM * IN_DIM; idx += MLP_THREADS) {
        const int i = idx / IN_DIM, k = idx - i * IN_DIM;
        sWpre [i * 21 + k] = Wpre[idx];
        sWpost[i * 21 + k] = Wpost[idx];
        sWsc  [i * 21 + k] = Wsc[idx];
    }
    if (tid < IN_DIM) {
        sb[tid]      = bpre[tid];
        sb[20 + tid] = bpost[tid] + bsc[tid];
    }
    // stage x slab: 320 contiguous floats
    sx[tid] = x[blockIdx.x * (NPB * IN_DIM) + tid];
    __syncthreads();

    const int ln = tid / IN_DIM;        // local node 0..15
    const int i  = tid - ln * IN_DIM;   // output channel 0..19
    const float* xr = &sx[ln * IN_DIM];

    // phase 1: pre[ln][i] = relu(bpre[i] + x . Wpre[i,:])
    float a = sb[i];
#pragma unroll
    for (int k = 0; k < IN_DIM; k++) a = fmaf(xr[k], sWpre[i * 21 + k], a);
    spre[ln * 21 + i] = fmaxf(a, 0.0f);
    __syncthreads();

    // phase 2: out = bpost[i]+bsc[i] + pre . Wpost[i,:] + x . Wsc[i,:]
    const float* pr = &spre[ln * 21];
    float b = sb[20 + i];
#pragma unroll
    for (int k = 0; k < IN_DIM; k++) {
        b = fmaf(pr[k], sWpost[i * 21 + k], b);
        b = fmaf(xr[k], sWsc [i * 21 + k], b);
    }
    out[(blockIdx.x * NPB + ln) * OUT_DIM + i] = b;
}

// ============================================================================
// K2: fused histogram + bucket scatter — the atomic return IS the slot.
//     slot = col*CAP + atomicAdd(count[col]). 2 edges / thread, 16 regs,
//     full occupancy to hide the ATOMG latency.
// ============================================================================
__global__ void k_hist_scatter(const int* __restrict__ ei)
{
    const int i = blockIdx.x * blockDim.x + threadIdx.x;
    if (i >= N_EDGES / 2) return;
    const int2 r = __ldg(&((const int2*)ei)[i]);
    const int2 c = __ldg(&((const int2*)(ei + N_EDGES))[i]);
    const int rk0 = atomicAdd(&g_count[c.x], 1);
    const int rk1 = atomicAdd(&g_count[c.y], 1);
    g_bucket[(c.x << 6) + rk0] = r.x;
    g_bucket[(c.y << 6) + rk1] = r.y;
}

// ============================================================================
// K3: fused SH + gather-aggregate. One warp per destination node.
//     Reads degree from g_count and re-zeros it (restores replay invariant).
//     Chunk of 32 edges: phase 1 = lane-parallel SH into SMEM;
//     phase 2 = serial accumulate with broadcast LDS.128 SH reads.
// ============================================================================
#define WPB 8   // warps per block (256 threads)

__global__ void k_aggr3(const float* __restrict__ x,
                        const float* __restrict__ pos,
                        float* __restrict__ out)
{
    __shared__ float s_sh[WPB][32][20];   // [warp][edge][sh1..sh15, pad..]
    __shared__ int   s_r [WPB][32];

    const int warp = (blockIdx.x * blockDim.x + threadIdx.x) >> 5;
    const int w    = (threadIdx.x >> 5);
    const int lane = threadIdx.x & 31;
    if (warp >= N_NODES) return;
    const int n = warp;

    const int deg = g_count[n];
    if (lane == 0) g_count[n] = 0;        // restore invariant for next replay
    const int s0 = n << 6;                // bucket base
    const int s1 = s0 + deg;

    const float pnx = pos[n * 3 + 0];
    const float pny = pos[n * 3 + 1];
    const float pnz = pos[n * 3 + 2];

    float accS = 0.0f;
    float acc[15];
#pragma unroll
    for (int j = 0; j < 15; j++) acc[j] = 0.0f;

    for (int base = s0; base < s1; base += 32) {
        const int m = min(32, s1 - base);

        // ---- phase 1: lane-parallel SH for this chunk ----
        if (lane < m) {
            const int r = g_bucket[base + lane];       // coalesced within bucket
            s_r[w][lane] = r;
            float rx = pnx - pos[r * 3 + 0];
            float ry = pny - pos[r * 3 + 1];
            float rz = pnz - pos[r * 3 + 2];
            float inv = rsqrtf(fmaf(rx, rx, fmaf(ry, ry, fmaf(rz, rz, 1e-12f))));
            float X = rx * inv, Y = ry * inv, Z = rz * inv;
            float X2 = X * X, Y2 = Y * Y, Z2 = Z * Z;

            float4* q = (float4*)&s_sh[w][lane][0];
            q[0] = make_float4(0.4886025119029199f * Y,
                               0.4886025119029199f * Z,
                               0.4886025119029199f * X,
                               1.0925484305920792f * X * Y);
            q[1] = make_float4(1.0925484305920792f * Y * Z,
                               0.31539156525252005f * (3.0f * Z2 - 1.0f),
                               1.0925484305920792f * X * Z,
                               0.5462742152960396f * (X2 - Y2));
            q[2] = make_float4(0.5900435899266435f * Y * (3.0f * X2 - Y2),
                               2.890611442640554f  * X * Y * Z,
                               0.4570457994644658f * Y * (5.0f * Z2 - 1.0f),
                               0.3731763325901154f * Z * (5.0f * Z2 - 3.0f));
            q[3] = make_float4(0.4570457994644658f * X * (5.0f * Z2 - 1.0f),
                               1.445305721320277f  * Z * (X2 - Y2),
                               0.5900435899266435f * X * (X2 - 3.0f * Y2),
                               0.0f);
        }
        __syncwarp();

        // ---- phase 2: serial accumulate (2x unrolled) ----
        const float4* shA;
        const float4* shB;
        int t = 0;
        for (; t + 2 <= m; t += 2) {
            const int rA = s_r[w][t];
            const int rB = s_r[w][t + 1];
            const float sA = (lane < IN_DIM) ? __ldg(&x[rA * IN_DIM + lane]) : 0.0f;
            const float sB = (lane < IN_DIM) ? __ldg(&x[rB * IN_DIM + lane]) : 0.0f;
            shA = (const float4*)&s_sh[w][t][0];
            shB = (const float4*)&s_sh[w][t + 1][0];
            const float4 a0 = shA[0], a1 = shA[1], a2 = shA[2], a3 = shA[3];
            const float4 b0 = shB[0], b1 = shB[1], b2 = shB[2], b3 = shB[3];

            accS += sA + sB;
            acc[0]  = fmaf(sA, a0.x, fmaf(sB, b0.x, acc[0]));
            acc[1]  = fmaf(sA, a0.y, fmaf(sB, b0.y, acc[1]));
            acc[2]  = fmaf(sA, a0.z, fmaf(sB, b0.z, acc[2]));
            acc[3]  = fmaf(sA, a0.w, fmaf(sB, b0.w, acc[3]));
            acc[4]  = fmaf(sA, a1.x, fmaf(sB, b1.x, acc[4]));
            acc[5]  = fmaf(sA, a1.y, fmaf(sB, b1.y, acc[5]));
            acc[6]  = fmaf(sA, a1.z, fmaf(sB, b1.z, acc[6]));
            acc[7]  = fmaf(sA, a1.w, fmaf(sB, b1.w, acc[7]));
            acc[8]  = fmaf(sA, a2.x, fmaf(sB, b2.x, acc[8]));
            acc[9]  = fmaf(sA, a2.y, fmaf(sB, b2.y, acc[9]));
            acc[10] = fmaf(sA, a2.z, fmaf(sB, b2.z, acc[10]));
            acc[11] = fmaf(sA, a2.w, fmaf(sB, b2.w, acc[11]));
            acc[12] = fmaf(sA, a3.x, fmaf(sB, b3.x, acc[12]));
            acc[13] = fmaf(sA, a3.y, fmaf(sB, b3.y, acc[13]));
            acc[14] = fmaf(sA, a3.z, fmaf(sB, b3.z, acc[14]));
        }
        if (t < m) {
            const int rA = s_r[w][t];
            const float sA = (lane < IN_DIM) ? __ldg(&x[rA * IN_DIM + lane]) : 0.0f;
            shA = (const float4*)&s_sh[w][t][0];
            const float4 a0 = shA[0], a1 = shA[1], a2 = shA[2], a3 = shA[3];
            accS += sA;
            acc[0]  = fmaf(sA, a0.x, acc[0]);
            acc[1]  = fmaf(sA, a0.y, acc[1]);
            acc[2]  = fmaf(sA, a0.z, acc[2]);
            acc[3]  = fmaf(sA, a0.w, acc[3]);
            acc[4]  = fmaf(sA, a1.x, acc[4]);
            acc[5]  = fmaf(sA, a1.y, acc[5]);
            acc[6]  = fmaf(sA, a1.z, acc[6]);
            acc[7]  = fmaf(sA, a1.w, acc[7]);
            acc[8]  = fmaf(sA, a2.x, acc[8]);
            acc[9]  = fmaf(sA, a2.y, acc[9]);
            acc[10] = fmaf(sA, a2.z, acc[10]);
            acc[11] = fmaf(sA, a2.w, acc[11]);
            acc[12] = fmaf(sA, a3.x, acc[12]);
            acc[13] = fmaf(sA, a3.y, acc[13]);
            acc[14] = fmaf(sA, a3.z, acc[14]);
        }
        __syncwarp();
    }

    if (lane < IN_DIM) {
        float* base = out + n * OUT_DIM;
        base[20 + lane] = accS;
        float4* p = (float4*)(base + 40 + lane * SH_DIM);
        p[0] = make_float4(accS * 0.28209479177387814f, acc[0],  acc[1],  acc[2]);
        p[1] = make_float4(acc[3],  acc[4],  acc[5],  acc[6]);
        p[2] = make_float4(acc[7],  acc[8],  acc[9],  acc[10]);
        p[3] = make_float4(acc[11], acc[12], acc[13], acc[14]);
    }
}

// ============================================================================
extern "C" void kernel_launch(void* const* d_in, const int* in_sizes, int n_in,
                              void* d_out, int out_size)
{
    const float* x     = (const float*)d_in[0];
    const float* pos   = (const float*)d_in[1];
    const int*   ei    = (const int*)  d_in[2];
    const float* Wpre  = (const float*)d_in[3];
    const float* bpre  = (const float*)d_in[4];
    const float* Wpost = (const float*)d_in[5];
    const float* bpost = (const float*)d_in[6];
    const float* Wsc   = (const float*)d_in[7];
    const float* bsc   = (const float*)d_in[8];
    float* out = (float*)d_out;

    k_mlp         <<<MLP_GRID, MLP_THREADS>>>(x, Wpre, bpre, Wpost, bpost,
                                              Wsc, bsc, out);
    k_hist_scatter<<<(N_EDGES / 2 + 255) / 256, 256>>>(ei);
    k_aggr3       <<<(N_NODES * 32 + 255) / 256, 256>>>(x, pos, out);
}

// round 14
// speedup vs baseline: 1.0324x; 1.0184x over previous
#include <cuda_runtime.h>

#define N_NODES 20000
#define N_EDGES 240000
#define IN_DIM  20
#define SH_DIM  16
#define OUT_DIM 360     // 20 (mlp) + 20 (sender sum) + 320 (tensor product)
#define CAP     64      // bucket capacity per node (max in-degree bound)

// ---- scratch (zero-initialized at module load; g_count invariant: ==0 on
//      entry to kernel_launch, restored by k_aggr each call) ----
__device__ __align__(16) int g_count[N_NODES];
__device__ __align__(16) int g_bucket[N_NODES * CAP];    // per-dest sender row ids

// ============================================================================
// K1: per-node MLP (output cols 0..19).
//     Thread = (node, output): 16 nodes x 20 outputs per 320-thread block.
//     All shared traffic vectorized: weight rows as float4 (stride 20),
//     x slab and pre read as broadcast LDS.128. ~25 LDS.128 + 60 FMA/thread.
// ============================================================================
#define NPB         16                   // nodes per block
#define MLP_THREADS (NPB * IN_DIM)       // 320
#define MLP_GRID    (N_NODES / NPB)      // 1250

__global__ void k_mlp(const float* __restrict__ x,
                      const float* __restrict__ Wpre,  const float* __restrict__ bpre,
                      const float* __restrict__ Wpost, const float* __restrict__ bpost,
                      const float* __restrict__ Wsc,   const float* __restrict__ bsc,
                      float* __restrict__ out)
{
    __shared__ float4 sWpre4[IN_DIM * 5], sWpost4[IN_DIM * 5], sWsc4[IN_DIM * 5];
    __shared__ float  sb[40];
    __shared__ float  sx  [NPB * IN_DIM];    // x slab (320 floats = 80 float4)
    __shared__ float  spre[NPB * IN_DIM];    // relu(pre), stride 20 (16B aligned)

    const int tid = threadIdx.x;

    // stage weights as float4 (100 float4 per matrix) and fused biases
    if (tid < 100)       sWpre4 [tid]       = ((const float4*)Wpre )[tid];
    else if (tid < 200)  sWpost4[tid - 100] = ((const float4*)Wpost)[tid - 100];
    else if (tid < 300)  sWsc4  [tid - 200] = ((const float4*)Wsc  )[tid - 200];
    if (tid < IN_DIM) {
        sb[tid]      = bpre[tid];
        sb[20 + tid] = bpost[tid] + bsc[tid];
    }
    if (tid < 80)
        ((float4*)sx)[tid] = ((const float4*)x)[blockIdx.x * 80 + tid];
    __syncthreads();

    const int ln = tid / IN_DIM;        // local node 0..15
    const int i  = tid - ln * IN_DIM;   // output channel 0..19

    // x row in registers (broadcast LDS.128)
    float4 xr[5];
#pragma unroll
    for (int j = 0; j < 5; j++) xr[j] = ((const float4*)(sx + ln * IN_DIM))[j];

    // phase 1: pre = relu(bpre + x . Wpre[i,:])
    float a = sb[i];
#pragma unroll
    for (int j = 0; j < 5; j++) {
        const float4 w = sWpre4[i * 5 + j];
        a = fmaf(xr[j].x, w.x, a);
        a = fmaf(xr[j].y, w.y, a);
        a = fmaf(xr[j].z, w.z, a);
        a = fmaf(xr[j].w, w.w, a);
    }
    spre[ln * IN_DIM + i] = fmaxf(a, 0.0f);
    __syncthreads();

    // phase 2: out = (bpost+bsc) + pre . Wpost[i,:] + x . Wsc[i,:]
    float b = sb[20 + i];
#pragma unroll
    for (int j = 0; j < 5; j++) {
        const float4 p  = ((const float4*)(spre + ln * IN_DIM))[j];
        const float4 w1 = sWpost4[i * 5 + j];
        const float4 w2 = sWsc4  [i * 5 + j];
        b = fmaf(p.x,     w1.x, b);
        b = fmaf(p.y,     w1.y, b);
        b = fmaf(p.z,     w1.z, b);
        b = fmaf(p.w,     w1.w, b);
        b = fmaf(xr[j].x, w2.x, b);
        b = fmaf(xr[j].y, w2.y, b);
        b = fmaf(xr[j].z, w2.z, b);
        b = fmaf(xr[j].w, w2.w, b);
    }
    out[(blockIdx.x * NPB + ln) * OUT_DIM + i] = b;
}

// ============================================================================
// K2: fused histogram + bucket scatter — the atomic return IS the slot.
// ============================================================================
__global__ void k_hist_scatter(const int* __restrict__ ei)
{
    const int i = blockIdx.x * blockDim.x + threadIdx.x;
    if (i >= N_EDGES / 2) return;
    const int2 r = __ldg(&((const int2*)ei)[i]);
    const int2 c = __ldg(&((const int2*)(ei + N_EDGES))[i]);
    const int rk0 = atomicAdd(&g_count[c.x], 1);
    const int rk1 = atomicAdd(&g_count[c.y], 1);
    g_bucket[(c.x << 6) + rk0] = r.x;
    g_bucket[(c.y << 6) + rk1] = r.y;
}

// ============================================================================
// K3: fused SH + gather-aggregate. One warp per destination node.
// ============================================================================
#define WPB 8   // warps per block (256 threads)

__global__ void k_aggr3(const float* __restrict__ x,
                        const float* __restrict__ pos,
                        float* __restrict__ out)
{
    __shared__ float s_sh[WPB][32][20];   // [warp][edge][sh1..sh15, pad..]
    __shared__ int   s_r [WPB][32];

    const int warp = (blockIdx.x * blockDim.x + threadIdx.x) >> 5;
    const int w    = (threadIdx.x >> 5);
    const int lane = threadIdx.x & 31;
    if (warp >= N_NODES) return;
    const int n = warp;

    const int deg = g_count[n];
    if (lane == 0) g_count[n] = 0;        // restore invariant for next replay
    const int s0 = n << 6;                // bucket base
    const int s1 = s0 + deg;

    const float pnx = pos[n * 3 + 0];
    const float pny = pos[n * 3 + 1];
    const float pnz = pos[n * 3 + 2];

    float accS = 0.0f;
    float acc[15];
#pragma unroll
    for (int j = 0; j < 15; j++) acc[j] = 0.0f;

    for (int base = s0; base < s1; base += 32) {
        const int m = min(32, s1 - base);

        // ---- phase 1: lane-parallel SH for this chunk ----
        if (lane < m) {
            const int r = g_bucket[base + lane];       // coalesced within bucket
            s_r[w][lane] = r;
            float rx = pnx - pos[r * 3 + 0];
            float ry = pny - pos[r * 3 + 1];
            float rz = pnz - pos[r * 3 + 2];
            float inv = rsqrtf(fmaf(rx, rx, fmaf(ry, ry, fmaf(rz, rz, 1e-12f))));
            float X = rx * inv, Y = ry * inv, Z = rz * inv;
            float X2 = X * X, Y2 = Y * Y, Z2 = Z * Z;

            float4* q = (float4*)&s_sh[w][lane][0];
            q[0] = make_float4(0.4886025119029199f * Y,
                               0.4886025119029199f * Z,
                               0.4886025119029199f * X,
                               1.0925484305920792f * X * Y);
            q[1] = make_float4(1.0925484305920792f * Y * Z,
                               0.31539156525252005f * (3.0f * Z2 - 1.0f),
                               1.0925484305920792f * X * Z,
                               0.5462742152960396f * (X2 - Y2));
            q[2] = make_float4(0.5900435899266435f * Y * (3.0f * X2 - Y2),
                               2.890611442640554f  * X * Y * Z,
                               0.4570457994644658f * Y * (5.0f * Z2 - 1.0f),
                               0.3731763325901154f * Z * (5.0f * Z2 - 3.0f));
            q[3] = make_float4(0.4570457994644658f * X * (5.0f * Z2 - 1.0f),
                               1.445305721320277f  * Z * (X2 - Y2),
                               0.5900435899266435f * X * (X2 - 3.0f * Y2),
                               0.0f);
        }
        __syncwarp();

        // ---- phase 2: serial accumulate (2x unrolled) ----
        const float4* shA;
        const float4* shB;
        int t = 0;
        for (; t + 2 <= m; t += 2) {
            const int rA = s_r[w][t];
            const int rB = s_r[w][t + 1];
            const float sA = (lane < IN_DIM) ? __ldg(&x[rA * IN_DIM + lane]) : 0.0f;
            const float sB = (lane < IN_DIM) ? __ldg(&x[rB * IN_DIM + lane]) : 0.0f;
            shA = (const float4*)&s_sh[w][t][0];
            shB = (const float4*)&s_sh[w][t + 1][0];
            const float4 a0 = shA[0], a1 = shA[1], a2 = shA[2], a3 = shA[3];
            const float4 b0 = shB[0], b1 = shB[1], b2 = shB[2], b3 = shB[3];

            accS += sA + sB;
            acc[0]  = fmaf(sA, a0.x, fmaf(sB, b0.x, acc[0]));
            acc[1]  = fmaf(sA, a0.y, fmaf(sB, b0.y, acc[1]));
            acc[2]  = fmaf(sA, a0.z, fmaf(sB, b0.z, acc[2]));
            acc[3]  = fmaf(sA, a0.w, fmaf(sB, b0.w, acc[3]));
            acc[4]  = fmaf(sA, a1.x, fmaf(sB, b1.x, acc[4]));
            acc[5]  = fmaf(sA, a1.y, fmaf(sB, b1.y, acc[5]));
            acc[6]  = fmaf(sA, a1.z, fmaf(sB, b1.z, acc[6]));
            acc[7]  = fmaf(sA, a1.w, fmaf(sB, b1.w, acc[7]));
            acc[8]  = fmaf(sA, a2.x, fmaf(sB, b2.x, acc[8]));
            acc[9]  = fmaf(sA, a2.y, fmaf(sB, b2.y, acc[9]));
            acc[10] = fmaf(sA, a2.z, fmaf(sB, b2.z, acc[10]));
            acc[11] = fmaf(sA, a2.w, fmaf(sB, b2.w, acc[11]));
            acc[12] = fmaf(sA, a3.x, fmaf(sB, b3.x, acc[12]));
            acc[13] = fmaf(sA, a3.y, fmaf(sB, b3.y, acc[13]));
            acc[14] = fmaf(sA, a3.z, fmaf(sB, b3.z, acc[14]));
        }
        if (t < m) {
            const int rA = s_r[w][t];
            const float sA = (lane < IN_DIM) ? __ldg(&x[rA * IN_DIM + lane]) : 0.0f;
            shA = (const float4*)&s_sh[w][t][0];
            const float4 a0 = shA[0], a1 = shA[1], a2 = shA[2], a3 = shA[3];
            accS += sA;
            acc[0]  = fmaf(sA, a0.x, acc[0]);
            acc[1]  = fmaf(sA, a0.y, acc[1]);
            acc[2]  = fmaf(sA, a0.z, acc[2]);
            acc[3]  = fmaf(sA, a0.w, acc[3]);
            acc[4]  = fmaf(sA, a1.x, acc[4]);
            acc[5]  = fmaf(sA, a1.y, acc[5]);
            acc[6]  = fmaf(sA, a1.z, acc[6]);
            acc[7]  = fmaf(sA, a1.w, acc[7]);
            acc[8]  = fmaf(sA, a2.x, acc[8]);
            acc[9]  = fmaf(sA, a2.y, acc[9]);
            acc[10] = fmaf(sA, a2.z, acc[10]);
            acc[11] = fmaf(sA, a2.w, acc[11]);
            acc[12] = fmaf(sA, a3.x, acc[12]);
            acc[13] = fmaf(sA, a3.y, acc[13]);
            acc[14] = fmaf(sA, a3.z, acc[14]);
        }
        __syncwarp();
    }

    if (lane < IN_DIM) {
        float* base = out + n * OUT_DIM;
        base[20 + lane] = accS;
        float4* p = (float4*)(base + 40 + lane * SH_DIM);
        p[0] = make_float4(accS * 0.28209479177387814f, acc[0],  acc[1],  acc[2]);
        p[1] = make_float4(acc[3],  acc[4],  acc[5],  acc[6]);
        p[2] = make_float4(acc[7],  acc[8],  acc[9],  acc[10]);
        p[3] = make_float4(acc[11], acc[12], acc[13], acc[14]);
    }
}

// ============================================================================
// Launcher: fork k_mlp onto a side stream (it is data-independent of the
// hist/aggr chain — disjoint output columns, disjoint scratch), join at end.
// Event fork/join is graph-capturable.
// ============================================================================
extern "C" void kernel_launch(void* const* d_in, const int* in_sizes, int n_in,
                              void* d_out, int out_size)
{
    const float* x     = (const float*)d_in[0];
    const float* pos   = (const float*)d_in[1];
    const int*   ei    = (const int*)  d_in[2];
    const float* Wpre  = (const float*)d_in[3];
    const float* bpre  = (const float*)d_in[4];
    const float* Wpost = (const float*)d_in[5];
    const float* bpost = (const float*)d_in[6];
    const float* Wsc   = (const float*)d_in[7];
    const float* bsc   = (const float*)d_in[8];
    float* out = (float*)d_out;

    cudaStream_t s2;
    cudaEvent_t  eFork, eJoin;
    cudaStreamCreateWithFlags(&s2, cudaStreamNonBlocking);
    cudaEventCreateWithFlags(&eFork, cudaEventDisableTiming);
    cudaEventCreateWithFlags(&eJoin, cudaEventDisableTiming);

    // fork: side stream inherits the capture dependency from stream 0
    cudaEventRecord(eFork, 0);
    cudaStreamWaitEvent(s2, eFork, 0);

    k_mlp<<<MLP_GRID, MLP_THREADS, 0, s2>>>(x, Wpre, bpre, Wpost, bpost,
                                            Wsc, bsc, out);
    cudaEventRecord(eJoin, s2);

    // main chain on stream 0
    k_hist_scatter<<<(N_EDGES / 2 + 255) / 256, 256>>>(ei);
    k_aggr3       <<<(N_NODES * 32 + 255) / 256, 256>>>(x, pos, out);

    // join: stream 0 completes only after k_mlp finishes
    cudaStreamWaitEvent(0, eJoin, 0);

    cudaEventDestroy(eFork);
    cudaEventDestroy(eJoin);
    cudaStreamDestroy(s2);
}

// round 15
// speedup vs baseline: 1.2058x; 1.1679x over previous
#include <cuda_runtime.h>

#define N_NODES 20000
#define N_EDGES 240000
#define IN_DIM  20
#define SH_DIM  16
#define OUT_DIM 360     // 20 (mlp) + 20 (sender sum) + 320 (tensor product)
#define CAP     64      // bucket capacity per node (max in-degree bound)

// ---- scratch (zero-initialized at module load; g_count invariant: ==0 on
//      entry to kernel_launch, restored by k_aggr each call) ----
__device__ __align__(16) int    g_count[N_NODES];
__device__ __align__(16) float4 g_pos4[N_NODES];          // packed positions
__device__ __align__(16) float4 g_bucket4[N_NODES * CAP]; // {ux,uy,uz, row-bits}

// ============================================================================
// K0: pack pos [N,3] -> float4 (so endpoint gathers are single LDG.128)
// ============================================================================
__global__ void k_prep(const float* __restrict__ pos)
{
    const int n = blockIdx.x * blockDim.x + threadIdx.x;
    if (n >= N_NODES) return;
    g_pos4[n] = make_float4(pos[3 * n], pos[3 * n + 1], pos[3 * n + 2], 0.0f);
}

// ============================================================================
// K1: per-node MLP (output cols 0..19). Forked onto a side stream.
// ============================================================================
#define NPB         16                   // nodes per block
#define MLP_THREADS (NPB * IN_DIM)       // 320
#define MLP_GRID    (N_NODES / NPB)      // 1250

__global__ void k_mlp(const float* __restrict__ x,
                      const float* __restrict__ Wpre,  const float* __restrict__ bpre,
                      const float* __restrict__ Wpost, const float* __restrict__ bpost,
                      const float* __restrict__ Wsc,   const float* __restrict__ bsc,
                      float* __restrict__ out)
{
    __shared__ float4 sWpre4[IN_DIM * 5], sWpost4[IN_DIM * 5], sWsc4[IN_DIM * 5];
    __shared__ float  sb[40];
    __shared__ float  sx  [NPB * IN_DIM];
    __shared__ float  spre[NPB * IN_DIM];

    const int tid = threadIdx.x;

    if (tid < 100)       sWpre4 [tid]       = ((const float4*)Wpre )[tid];
    else if (tid < 200)  sWpost4[tid - 100] = ((const float4*)Wpost)[tid - 100];
    else if (tid < 300)  sWsc4  [tid - 200] = ((const float4*)Wsc  )[tid - 200];
    if (tid < IN_DIM) {
        sb[tid]      = bpre[tid];
        sb[20 + tid] = bpost[tid] + bsc[tid];
    }
    if (tid < 80)
        ((float4*)sx)[tid] = ((const float4*)x)[blockIdx.x * 80 + tid];
    __syncthreads();

    const int ln = tid / IN_DIM;
    const int i  = tid - ln * IN_DIM;

    float4 xr[5];
#pragma unroll
    for (int j = 0; j < 5; j++) xr[j] = ((const float4*)(sx + ln * IN_DIM))[j];

    float a = sb[i];
#pragma unroll
    for (int j = 0; j < 5; j++) {
        const float4 w = sWpre4[i * 5 + j];
        a = fmaf(xr[j].x, w.x, a);
        a = fmaf(xr[j].y, w.y, a);
        a = fmaf(xr[j].z, w.z, a);
        a = fmaf(xr[j].w, w.w, a);
    }
    spre[ln * IN_DIM + i] = fmaxf(a, 0.0f);
    __syncthreads();

    float b = sb[20 + i];
#pragma unroll
    for (int j = 0; j < 5; j++) {
        const float4 p  = ((const float4*)(spre + ln * IN_DIM))[j];
        const float4 w1 = sWpost4[i * 5 + j];
        const float4 w2 = sWsc4  [i * 5 + j];
        b = fmaf(p.x,     w1.x, b);
        b = fmaf(p.y,     w1.y, b);
        b = fmaf(p.z,     w1.z, b);
        b = fmaf(p.w,     w1.w, b);
        b = fmaf(xr[j].x, w2.x, b);
        b = fmaf(xr[j].y, w2.y, b);
        b = fmaf(xr[j].z, w2.z, b);
        b = fmaf(xr[j].w, w2.w, b);
    }
    out[(blockIdx.x * NPB + ln) * OUT_DIM + i] = b;
}

// ============================================================================
// K2: fused histogram + geometry + bucket scatter (slack kernel absorbs the
//     endpoint gathers and rsqrt). Per edge: 2 LDG.128 pos gathers, unit
//     vector, atomic rank, ONE scattered STG.128 {ux,uy,uz,row}.
// ============================================================================
__global__ void k_hist_scatter(const int* __restrict__ ei)
{
    const int i = blockIdx.x * blockDim.x + threadIdx.x;
    if (i >= N_EDGES / 2) return;
    const int2 r = __ldg(&((const int2*)ei)[i]);
    const int2 c = __ldg(&((const int2*)(ei + N_EDGES))[i]);

    const float4 pr0 = g_pos4[r.x];
    const float4 pc0 = g_pos4[c.x];
    const float4 pr1 = g_pos4[r.y];
    const float4 pc1 = g_pos4[c.y];

    float ax = pc0.x - pr0.x, ay = pc0.y - pr0.y, az = pc0.z - pr0.z;
    float ia = rsqrtf(fmaf(ax, ax, fmaf(ay, ay, fmaf(az, az, 1e-12f))));
    float bx = pc1.x - pr1.x, by = pc1.y - pr1.y, bz = pc1.z - pr1.z;
    float ib = rsqrtf(fmaf(bx, bx, fmaf(by, by, fmaf(bz, bz, 1e-12f))));

    const int rk0 = atomicAdd(&g_count[c.x], 1);
    const int rk1 = atomicAdd(&g_count[c.y], 1);
    g_bucket4[(c.x << 6) + rk0] = make_float4(ax * ia, ay * ia, az * ia,
                                              __int_as_float(r.x));
    g_bucket4[(c.y << 6) + rk1] = make_float4(bx * ib, by * ib, bz * ib,
                                              __int_as_float(r.y));
}

// ============================================================================
// K3: fused SH + gather-aggregate. One warp per destination node.
//     Phase 1 is now: ONE coalesced LDG.128 per lane + pure SH polynomial
//     (no pos gather, no rsqrt). Phase 2 unchanged.
// ============================================================================
#define WPB 8   // warps per block (256 threads)

__global__ void k_aggr3(const float* __restrict__ x,
                        float* __restrict__ out)
{
    __shared__ float s_sh[WPB][32][20];   // [warp][edge][sh1..sh15, pad..]
    __shared__ int   s_r [WPB][32];

    const int warp = (blockIdx.x * blockDim.x + threadIdx.x) >> 5;
    const int w    = (threadIdx.x >> 5);
    const int lane = threadIdx.x & 31;
    if (warp >= N_NODES) return;
    const int n = warp;

    const int deg = g_count[n];
    if (lane == 0) g_count[n] = 0;        // restore invariant for next replay
    const int s0 = n << 6;                // bucket base
    const int s1 = s0 + deg;

    float accS = 0.0f;
    float acc[15];
#pragma unroll
    for (int j = 0; j < 15; j++) acc[j] = 0.0f;

    for (int base = s0; base < s1; base += 32) {
        const int m = min(32, s1 - base);

        // ---- phase 1: lane-parallel SH (coalesced bucket read) ----
        if (lane < m) {
            const float4 u = g_bucket4[base + lane];   // coalesced LDG.128
            s_r[w][lane] = __float_as_int(u.w);
            const float X = u.x, Y = u.y, Z = u.z;
            const float X2 = X * X, Y2 = Y * Y, Z2 = Z * Z;

            float4* q = (float4*)&s_sh[w][lane][0];
            q[0] = make_float4(0.4886025119029199f * Y,
                               0.4886025119029199f * Z,
                               0.4886025119029199f * X,
                               1.0925484305920792f * X * Y);
            q[1] = make_float4(1.0925484305920792f * Y * Z,
                               0.31539156525252005f * (3.0f * Z2 - 1.0f),
                               1.0925484305920792f * X * Z,
                               0.5462742152960396f * (X2 - Y2));
            q[2] = make_float4(0.5900435899266435f * Y * (3.0f * X2 - Y2),
                               2.890611442640554f  * X * Y * Z,
                               0.4570457994644658f * Y * (5.0f * Z2 - 1.0f),
                               0.3731763325901154f * Z * (5.0f * Z2 - 3.0f));
            q[3] = make_float4(0.4570457994644658f * X * (5.0f * Z2 - 1.0f),
                               1.445305721320277f  * Z * (X2 - Y2),
                               0.5900435899266435f * X * (X2 - 3.0f * Y2),
                               0.0f);
        }
        __syncwarp();

        // ---- phase 2: serial accumulate (2x unrolled) ----
        const float4* shA;
        const float4* shB;
        int t = 0;
        for (; t + 2 <= m; t += 2) {
            const int rA = s_r[w][t];
            const int rB = s_r[w][t + 1];
            const float sA = (lane < IN_DIM) ? __ldg(&x[rA * IN_DIM + lane]) : 0.0f;
            const float sB = (lane < IN_DIM) ? __ldg(&x[rB * IN_DIM + lane]) : 0.0f;
            shA = (const float4*)&s_sh[w][t][0];
            shB = (const float4*)&s_sh[w][t + 1][0];
            const float4 a0 = shA[0], a1 = shA[1], a2 = shA[2], a3 = shA[3];
            const float4 b0 = shB[0], b1 = shB[1], b2 = shB[2], b3 = shB[3];

            accS += sA + sB;
            acc[0]  = fmaf(sA, a0.x, fmaf(sB, b0.x, acc[0]));
            acc[1]  = fmaf(sA, a0.y, fmaf(sB, b0.y, acc[1]));
            acc[2]  = fmaf(sA, a0.z, fmaf(sB, b0.z, acc[2]));
            acc[3]  = fmaf(sA, a0.w, fmaf(sB, b0.w, acc[3]));
            acc[4]  = fmaf(sA, a1.x, fmaf(sB, b1.x, acc[4]));
            acc[5]  = fmaf(sA, a1.y, fmaf(sB, b1.y, acc[5]));
            acc[6]  = fmaf(sA, a1.z, fmaf(sB, b1.z, acc[6]));
            acc[7]  = fmaf(sA, a1.w, fmaf(sB, b1.w, acc[7]));
            acc[8]  = fmaf(sA, a2.x, fmaf(sB, b2.x, acc[8]));
            acc[9]  = fmaf(sA, a2.y, fmaf(sB, b2.y, acc[9]));
            acc[10] = fmaf(sA, a2.z, fmaf(sB, b2.z, acc[10]));
            acc[11] = fmaf(sA, a2.w, fmaf(sB, b2.w, acc[11]));
            acc[12] = fmaf(sA, a3.x, fmaf(sB, b3.x, acc[12]));
            acc[13] = fmaf(sA, a3.y, fmaf(sB, b3.y, acc[13]));
            acc[14] = fmaf(sA, a3.z, fmaf(sB, b3.z, acc[14]));
        }
        if (t < m) {
            const int rA = s_r[w][t];
            const float sA = (lane < IN_DIM) ? __ldg(&x[rA * IN_DIM + lane]) : 0.0f;
            shA = (const float4*)&s_sh[w][t][0];
            const float4 a0 = shA[0], a1 = shA[1], a2 = shA[2], a3 = shA[3];
            accS += sA;
            acc[0]  = fmaf(sA, a0.x, acc[0]);
            acc[1]  = fmaf(sA, a0.y, acc[1]);
            acc[2]  = fmaf(sA, a0.z, acc[2]);
            acc[3]  = fmaf(sA, a0.w, acc[3]);
            acc[4]  = fmaf(sA, a1.x, acc[4]);
            acc[5]  = fmaf(sA, a1.y, acc[5]);
            acc[6]  = fmaf(sA, a1.z, acc[6]);
            acc[7]  = fmaf(sA, a1.w, acc[7]);
            acc[8]  = fmaf(sA, a2.x, acc[8]);
            acc[9]  = fmaf(sA, a2.y, acc[9]);
            acc[10] = fmaf(sA, a2.z, acc[10]);
            acc[11] = fmaf(sA, a2.w, acc[11]);
            acc[12] = fmaf(sA, a3.x, acc[12]);
            acc[13] = fmaf(sA, a3.y, acc[13]);
            acc[14] = fmaf(sA, a3.z, acc[14]);
        }
        __syncwarp();
    }

    if (lane < IN_DIM) {
        float* base = out + n * OUT_DIM;
        base[20 + lane] = accS;
        float4* p = (float4*)(base + 40 + lane * SH_DIM);
        p[0] = make_float4(accS * 0.28209479177387814f, acc[0],  acc[1],  acc[2]);
        p[1] = make_float4(acc[3],  acc[4],  acc[5],  acc[6]);
        p[2] = make_float4(acc[7],  acc[8],  acc[9],  acc[10]);
        p[3] = make_float4(acc[11], acc[12], acc[13], acc[14]);
    }
}

// ============================================================================
// Launcher: stream0 = prep -> hist_scatter -> aggr3; mlp forked on side
// stream (data-independent: disjoint out columns, disjoint scratch).
// ============================================================================
extern "C" void kernel_launch(void* const* d_in, const int* in_sizes, int n_in,
                              void* d_out, int out_size)
{
    const float* x     = (const float*)d_in[0];
    const float* pos   = (const float*)d_in[1];
    const int*   ei    = (const int*)  d_in[2];
    const float* Wpre  = (const float*)d_in[3];
    const float* bpre  = (const float*)d_in[4];
    const float* Wpost = (const float*)d_in[5];
    const float* bpost = (const float*)d_in[6];
    const float* Wsc   = (const float*)d_in[7];
    const float* bsc   = (const float*)d_in[8];
    float* out = (float*)d_out;

    cudaStream_t s2;
    cudaEvent_t  eFork, eJoin;
    cudaStreamCreateWithFlags(&s2, cudaStreamNonBlocking);
    cudaEventCreateWithFlags(&eFork, cudaEventDisableTiming);
    cudaEventCreateWithFlags(&eJoin, cudaEventDisableTiming);

    cudaEventRecord(eFork, 0);
    cudaStreamWaitEvent(s2, eFork, 0);

    k_mlp<<<MLP_GRID, MLP_THREADS, 0, s2>>>(x, Wpre, bpre, Wpost, bpost,
                                            Wsc, bsc, out);
    cudaEventRecord(eJoin, s2);

    k_prep        <<<(N_NODES + 255) / 256, 256>>>(pos);
    k_hist_scatter<<<(N_EDGES / 2 + 255) / 256, 256>>>(ei);
    k_aggr3       <<<(N_NODES * 32 + 255) / 256, 256>>>(x, out);

    cudaStreamWaitEvent(0, eJoin, 0);

    cudaEventDestroy(eFork);
    cudaEventDestroy(eJoin);
    cudaStreamDestroy(s2);
}